// round 1
// baseline (speedup 1.0000x reference)
#include <cuda_runtime.h>

#define D 64
#define MAXROWS 616000

// Scratch (device globals: allocation-free rule)
__device__ float g_core[(size_t)MAXROWS * D];
__device__ float g_gate[(size_t)MAXROWS * D];
__device__ float g_stats[4 * D];   // sum_c[64] | sumsq_c[64] | sum_g[64] | sumsq_g[64]
__device__ float g_norm[4 * D];    // scale_c[64] | shift_c[64] | scale_g[64] | shift_g[64]

// ---------------------------------------------------------------------------
// Pass 1: fused gather + dual GEMV (core & gate) + per-feature sum/sumsq stats
// Block = 256 threads, persistent (grid-stride over 64-row tiles).
// Shared: sW[K][128] (Wc|Wg), sX[K][64] (input tile, k-major), sStat[256].
// Thread computes an 8-row x 4-col register tile: 32 FFMA per k vs 3 LDS.
// ---------------------------------------------------------------------------
template<int K, int NSEG>
__global__ void __launch_bounds__(256, 1) pass1_kernel(
    const float* __restrict__ b0, const int* __restrict__ i0,
    const float* __restrict__ b1, const int* __restrict__ i1,
    const float* __restrict__ b2, const int* __restrict__ i2,
    const float* __restrict__ b3, const int* __restrict__ i3,
    const float* __restrict__ Wc, const float* __restrict__ Wg,
    int R)
{
    extern __shared__ float smem[];
    float* sW    = smem;               // K*128
    float* sX    = smem + K * 128;     // K*64
    float* sStat = sX + K * 64;        // 256

    const int tid = threadIdx.x;

    // Load combined weights (once per block)
    for (int idx = tid; idx < K * 128; idx += 256) {
        int k = idx >> 7, c = idx & 127;
        sW[idx] = (c < 64) ? Wc[k * 64 + c] : Wg[k * 64 + (c - 64)];
    }
    sStat[tid] = 0.f;
    __syncthreads();

    const int colg = tid & 31;   // column group: cols colg*4 .. colg*4+3 (of 128)
    const int rowg = tid >> 5;   // row group: rows rowg*8 .. rowg*8+7 (of 64)

    float ssum[4] = {0.f, 0.f, 0.f, 0.f};
    float ssq[4]  = {0.f, 0.f, 0.f, 0.f};

    const int ntiles = (R + 63) >> 6;
    for (int tile = blockIdx.x; tile < ntiles; tile += gridDim.x) {
        const int base = tile << 6;

        // Load gathered tile, transposed: sX[k][row]
        for (int idx = tid; idx < 64 * (K / 4); idx += 256) {
            int row = idx & 63;
            int q   = idx >> 6;               // float4 index within row
            int grow = base + row;
            float4 v = make_float4(0.f, 0.f, 0.f, 0.f);
            if (grow < R) {
                int seg = q >> 4;             // 16 float4 per 64-float segment
                int off = q & 15;
                const float* bp; const int* ip;
                if (seg == 0)      { bp = b0; ip = i0; }
                else if (seg == 1) { bp = b1; ip = i1; }
                else if (seg == 2) { bp = b2; ip = i2; }
                else               { bp = b3; ip = i3; }
                int srow = ip ? ip[grow] : grow;
                v = *reinterpret_cast<const float4*>(bp + (size_t)srow * 64 + off * 4);
            }
            int kk = q * 4;
            sX[(kk + 0) * 64 + row] = v.x;
            sX[(kk + 1) * 64 + row] = v.y;
            sX[(kk + 2) * 64 + row] = v.z;
            sX[(kk + 3) * 64 + row] = v.w;
        }
        __syncthreads();

        float acc[8][4];
        #pragma unroll
        for (int r = 0; r < 8; r++)
            #pragma unroll
            for (int c = 0; c < 4; c++) acc[r][c] = 0.f;

        #pragma unroll 4
        for (int k = 0; k < K; k++) {
            float4 xa = *reinterpret_cast<float4*>(&sX[k * 64 + rowg * 8]);
            float4 xb = *reinterpret_cast<float4*>(&sX[k * 64 + rowg * 8 + 4]);
            float4 w  = *reinterpret_cast<float4*>(&sW[k * 128 + colg * 4]);
            float xs[8] = {xa.x, xa.y, xa.z, xa.w, xb.x, xb.y, xb.z, xb.w};
            float ws[4] = {w.x, w.y, w.z, w.w};
            #pragma unroll
            for (int r = 0; r < 8; r++)
                #pragma unroll
                for (int c = 0; c < 4; c++)
                    acc[r][c] += xs[r] * ws[c];
        }

        // Store outputs + accumulate stats (valid rows only)
        const int cg = colg * 4;                      // combined col 0..124
        float* outp = (cg < 64) ? g_core : g_gate;
        const int ocol = (cg < 64) ? cg : cg - 64;
        #pragma unroll
        for (int r = 0; r < 8; r++) {
            int grow = base + rowg * 8 + r;
            if (grow < R) {
                float4 v = make_float4(acc[r][0], acc[r][1], acc[r][2], acc[r][3]);
                *reinterpret_cast<float4*>(outp + (size_t)grow * 64 + ocol) = v;
                #pragma unroll
                for (int c = 0; c < 4; c++) {
                    ssum[c] += acc[r][c];
                    ssq[c]  += acc[r][c] * acc[r][c];
                }
            }
        }
        __syncthreads();
    }

    // Reduce stats: registers -> shared -> global
    {
        const int cg = colg * 4;
        const int sbase = (cg < 64) ? 0 : 128;
        const int ocol  = (cg < 64) ? cg : cg - 64;
        #pragma unroll
        for (int c = 0; c < 4; c++) {
            atomicAdd(&sStat[sbase + ocol + c], ssum[c]);
            atomicAdd(&sStat[sbase + 64 + ocol + c], ssq[c]);
        }
    }
    __syncthreads();
    atomicAdd(&g_stats[tid], sStat[tid]);
}

// ---------------------------------------------------------------------------
// Pass 2: finalize BN scale/shift from global stats (1 block, 128 threads)
// ---------------------------------------------------------------------------
__global__ void finalize_kernel(const float* __restrict__ gc, const float* __restrict__ bc,
                                const float* __restrict__ gg, const float* __restrict__ bg,
                                float invR)
{
    int t = threadIdx.x;  // 0..127
    if (t < 64) {
        float mean = g_stats[t] * invR;
        float var  = fmaxf(g_stats[64 + t] * invR - mean * mean, 0.f);
        float sc   = gc[t] * rsqrtf(var + 1e-5f);
        g_norm[t]      = sc;
        g_norm[64 + t] = bc[t] - mean * sc;
    } else {
        int c = t - 64;
        float mean = g_stats[128 + c] * invR;
        float var  = fmaxf(g_stats[192 + c] * invR - mean * mean, 0.f);
        float sc   = gg[c] * rsqrtf(var + 1e-5f);
        g_norm[128 + c] = sc;
        g_norm[192 + c] = bg[c] - mean * sc;
    }
}

__device__ __forceinline__ float sigm(float x) { return 1.f / (1.f + __expf(-x)); }

// ---------------------------------------------------------------------------
// Pass 3a: BN + silu*sigmoid + atomic segment scatter into S
// ---------------------------------------------------------------------------
__global__ void apply_scatter_kernel(const int* __restrict__ seg, float* __restrict__ S, int R)
{
    int idx = blockIdx.x * blockDim.x + threadIdx.x;
    if (idx >= R * 16) return;
    int row = idx >> 4;
    int col = (idx & 15) * 4;
    float4 c4 = *reinterpret_cast<const float4*>(g_core + (size_t)row * 64 + col);
    float4 g4 = *reinterpret_cast<const float4*>(g_gate + (size_t)row * 64 + col);
    float cs[4] = {c4.x, c4.y, c4.z, c4.w};
    float gs[4] = {g4.x, g4.y, g4.z, g4.w};
    int s = seg[row];
    float* dst = S + (size_t)s * 64 + col;
    #pragma unroll
    for (int j = 0; j < 4; j++) {
        float cn = cs[j] * g_norm[col + j] + g_norm[64 + col + j];
        float gn = gs[j] * g_norm[128 + col + j] + g_norm[192 + col + j];
        float m  = cn * sigm(cn) * sigm(gn);
        atomicAdd(dst + j, m);
    }
}

// ---------------------------------------------------------------------------
// Pass 3b: BN + silu*sigmoid + residual write (angle stage, no scatter)
// ---------------------------------------------------------------------------
__global__ void apply_write_kernel(const float* __restrict__ angle, float* __restrict__ dst, int R)
{
    int idx = blockIdx.x * blockDim.x + threadIdx.x;
    if (idx >= R * 16) return;
    int row = idx >> 4;
    int col = (idx & 15) * 4;
    float4 c4 = *reinterpret_cast<const float4*>(g_core + (size_t)row * 64 + col);
    float4 g4 = *reinterpret_cast<const float4*>(g_gate + (size_t)row * 64 + col);
    float4 a4 = *reinterpret_cast<const float4*>(angle + (size_t)row * 64 + col);
    float cs[4] = {c4.x, c4.y, c4.z, c4.w};
    float gs[4] = {g4.x, g4.y, g4.z, g4.w};
    float as[4] = {a4.x, a4.y, a4.z, a4.w};
    float o[4];
    #pragma unroll
    for (int j = 0; j < 4; j++) {
        float cn = cs[j] * g_norm[col + j] + g_norm[64 + col + j];
        float gn = gs[j] * g_norm[128 + col + j] + g_norm[192 + col + j];
        o[j] = cn * sigm(cn) * sigm(gn) + as[j];
    }
    *reinterpret_cast<float4*>(dst + (size_t)row * 64 + col) =
        make_float4(o[0], o[1], o[2], o[3]);
}

// ---------------------------------------------------------------------------
// Pass 4: in-place row transform: S[r,:] = S[r,:] @ W(64x64) + resid[r,:]
// Warp per row; W in shared (16 KB), per-warp row buffer in shared.
// ---------------------------------------------------------------------------
__global__ void __launch_bounds__(256) rowxform_kernel(
    float* __restrict__ S, const float* __restrict__ W,
    const float* __restrict__ resid, int R)
{
    __shared__ float sW2[64 * 64];
    __shared__ float sRow[8][64];
    const int tid  = threadIdx.x;
    const int warp = tid >> 5;
    const int lane = tid & 31;

    for (int idx = tid; idx < 64 * 64; idx += 256) sW2[idx] = W[idx];
    __syncthreads();

    for (int row = blockIdx.x * 8 + warp; row < R; row += gridDim.x * 8) {
        sRow[warp][lane]      = S[(size_t)row * 64 + lane];
        sRow[warp][lane + 32] = S[(size_t)row * 64 + lane + 32];
        __syncwarp();
        float a0 = 0.f, a1 = 0.f;
        #pragma unroll
        for (int k = 0; k < 64; k++) {
            float v = sRow[warp][k];
            a0 += v * sW2[k * 64 + lane];
            a1 += v * sW2[k * 64 + lane + 32];
        }
        S[(size_t)row * 64 + lane]      = a0 + resid[(size_t)row * 64 + lane];
        S[(size_t)row * 64 + lane + 32] = a1 + resid[(size_t)row * 64 + lane + 32];
        __syncwarp();
    }
}

// ---------------------------------------------------------------------------
// Host orchestration
// ---------------------------------------------------------------------------
extern "C" void kernel_launch(void* const* d_in, const int* in_sizes, int n_in,
                              void* d_out, int out_size)
{
    // Two plausible metadata orderings: reference-signature order vs
    // setup_inputs dict order. Disambiguate: in signature order, slot 3 is
    // Wc_atom (3*64*64 = 12288 elems); in dict order it is edge_index (2E).
    const bool dictOrder = (n_in >= 4) && (in_sizes[3] > 100000);

    const float *vfeat = (const float*)d_in[0];
    const float *efeat = (const float*)d_in[1];
    const float *afeat = (const float*)d_in[2];
    const float *WcA, *WgA, *WoA, *WcB, *WgB, *WoB, *WcC, *WgC;
    const float *gac, *bac, *gag, *bag, *gbc, *bbc, *gbg, *bbg, *gnc, *bnc, *gng, *bng;
    const int *eidx, *kidx, *iidx, *jidx;

    if (dictOrder) {
        eidx = (const int*)d_in[3];  kidx = (const int*)d_in[4];
        iidx = (const int*)d_in[5];  jidx = (const int*)d_in[6];
        WcA = (const float*)d_in[7];  WgA = (const float*)d_in[8];  WoA = (const float*)d_in[9];
        WcB = (const float*)d_in[10]; WgB = (const float*)d_in[11]; WoB = (const float*)d_in[12];
        WcC = (const float*)d_in[13]; WgC = (const float*)d_in[14];
        gac = (const float*)d_in[15]; gag = (const float*)d_in[16];
        gbc = (const float*)d_in[17]; gbg = (const float*)d_in[18];
        gnc = (const float*)d_in[19]; gng = (const float*)d_in[20];
        bac = (const float*)d_in[21]; bag = (const float*)d_in[22];
        bbc = (const float*)d_in[23]; bbg = (const float*)d_in[24];
        bnc = (const float*)d_in[25]; bng = (const float*)d_in[26];
    } else {
        WcA = (const float*)d_in[3];  WgA = (const float*)d_in[4];  WoA = (const float*)d_in[5];
        WcB = (const float*)d_in[6];  WgB = (const float*)d_in[7];  WoB = (const float*)d_in[8];
        WcC = (const float*)d_in[9];  WgC = (const float*)d_in[10];
        gac = (const float*)d_in[11]; bac = (const float*)d_in[12];
        gag = (const float*)d_in[13]; bag = (const float*)d_in[14];
        gbc = (const float*)d_in[15]; bbc = (const float*)d_in[16];
        gbg = (const float*)d_in[17]; bbg = (const float*)d_in[18];
        gnc = (const float*)d_in[19]; bnc = (const float*)d_in[20];
        gng = (const float*)d_in[21]; bng = (const float*)d_in[22];
        eidx = (const int*)d_in[23]; kidx = (const int*)d_in[24];
        iidx = (const int*)d_in[25]; jidx = (const int*)d_in[26];
    }

    const int N = in_sizes[0] / 64;
    const int E = in_sizes[1] / 64;
    const int T = in_sizes[2] / 64;
    const int* src = eidx;
    const int* dst = eidx + E;

    float* out  = (float*)d_out;
    float* vnew = out;                          // [N,64]
    float* enew = out + (size_t)N * 64;         // [E,64]
    float* anew = out + (size_t)(N + E) * 64;   // [T,64]

    float* stats_ptr = nullptr;
    cudaGetSymbolAddress((void**)&stats_ptr, g_stats);

    int dev = 0;  cudaGetDevice(&dev);
    int sm = 148; cudaDeviceGetAttribute(&sm, cudaDevAttrMultiProcessorCount, dev);

    const size_t smemA = (size_t)(192 * 128 + 192 * 64 + 256) * 4;  // ~145 KB
    const size_t smemB = (size_t)(256 * 128 + 256 * 64 + 256) * 4;  // ~193 KB
    cudaFuncSetAttribute(pass1_kernel<192, 3>, cudaFuncAttributeMaxDynamicSharedMemorySize, (int)smemA);
    cudaFuncSetAttribute(pass1_kernel<256, 4>, cudaFuncAttributeMaxDynamicSharedMemorySize, (int)smemB);

    // Zero segment-sum accumulators (d_out is poisoned by the harness)
    cudaMemsetAsync(vnew, 0, (size_t)N * 64 * sizeof(float));
    cudaMemsetAsync(enew, 0, (size_t)E * 64 * sizeof(float));

    // ---------------- Stage A: AtomConvCat ----------------
    cudaMemsetAsync(stats_ptr, 0, 256 * sizeof(float));
    pass1_kernel<192, 3><<<sm, 256, smemA>>>(
        vfeat, src, efeat, nullptr, vfeat, dst, nullptr, nullptr, WcA, WgA, E);
    finalize_kernel<<<1, 128>>>(gac, bac, gag, bag, 1.f / (float)E);
    apply_scatter_kernel<<<(E * 16 + 255) / 256, 256>>>(src, vnew, E);
    rowxform_kernel<<<sm * 4, 256>>>(vnew, WoA, vfeat, N);

    // ---------------- Stage B: BondConvCat ----------------
    cudaMemsetAsync(stats_ptr, 0, 256 * sizeof(float));
    pass1_kernel<256, 4><<<sm, 256, smemB>>>(
        vnew, jidx, efeat, kidx, efeat, iidx, afeat, nullptr, WcB, WgB, T);
    finalize_kernel<<<1, 128>>>(gbc, bbc, gbg, bbg, 1.f / (float)T);
    apply_scatter_kernel<<<(T * 16 + 255) / 256, 256>>>(kidx, enew, T);
    rowxform_kernel<<<sm * 4, 256>>>(enew, WoB, efeat, E);

    // ---------------- Stage C: AngleConvCat ----------------
    cudaMemsetAsync(stats_ptr, 0, 256 * sizeof(float));
    pass1_kernel<256, 4><<<sm, 256, smemB>>>(
        vnew, jidx, enew, kidx, enew, iidx, afeat, nullptr, WcC, WgC, T);
    finalize_kernel<<<1, 128>>>(gnc, bnc, gng, bng, 1.f / (float)T);
    apply_write_kernel<<<(T * 16 + 255) / 256, 256>>>(afeat, anew, T);
}

// round 2
// speedup vs baseline: 1.5602x; 1.5602x over previous
#include <cuda_runtime.h>
#include <cstdint>

#define D 64
#define MAXROWS 616000

// Scratch (device globals: allocation-free rule)
__device__ float g_core[(size_t)MAXROWS * D];
__device__ float g_gate[(size_t)MAXROWS * D];
__device__ float g_stats[4 * D];   // sum_c[64] | sumsq_c[64] | sum_g[64] | sumsq_g[64]
__device__ float g_norm[4 * D];    // scale_c[64] | shift_c[64] | scale_g[64] | shift_g[64]

__device__ __forceinline__ uint32_t f2tf(float f) {
    uint32_t r; asm("cvt.rna.tf32.f32 %0, %1;" : "=r"(r) : "f"(f)); return r;
}
__device__ __forceinline__ float f2tff(float f) { return __uint_as_float(f2tf(f)); }

// m16n8k8 tf32 mma, D += A*B
__device__ __forceinline__ void mma8(float c[4], const uint32_t a[4], const uint32_t b[2]) {
    asm volatile("mma.sync.aligned.m16n8k8.row.col.f32.tf32.tf32.f32 "
        "{%0,%1,%2,%3}, {%4,%5,%6,%7}, {%8,%9}, {%0,%1,%2,%3};\n"
        : "+f"(c[0]), "+f"(c[1]), "+f"(c[2]), "+f"(c[3])
        : "r"(a[0]), "r"(a[1]), "r"(a[2]), "r"(a[3]), "r"(b[0]), "r"(b[1]));
}

// ---------------------------------------------------------------------------
// Pass 1 (tf32 tensor-core version):
// fused gather + dual GEMM (core|gate combined, 128 cols) + per-feature stats.
// Block = 256 threads (8 warps), persistent over 64-row tiles.
// Warp tile: 32 rows x 32 cols (wr = wid>>2 in {0,1}, wc = wid&3 in {0..3}).
// Shared: sW [K][128] swizzled (c ^ ((k&3)<<3)), sA [64][K] swizzled
// (k ^ ((row&7)<<2)) -> conflict-free fragment LDS, no padding.
// ---------------------------------------------------------------------------
template<int K>
__global__ void __launch_bounds__(256, 1) pass1_mma(
    const float* __restrict__ b0, const int* __restrict__ i0,
    const float* __restrict__ b1, const int* __restrict__ i1,
    const float* __restrict__ b2, const int* __restrict__ i2,
    const float* __restrict__ b3, const int* __restrict__ i3,
    const float* __restrict__ Wc, const float* __restrict__ Wg,
    int R)
{
    extern __shared__ float smem[];
    float* sW    = smem;               // K*128
    float* sA    = smem + K * 128;     // 64*K
    float* sStat = sA + 64 * K;        // 256

    const int tid  = threadIdx.x;
    const int lane = tid & 31, wid = tid >> 5;
    const int wr = wid >> 2, wc = wid & 3;
    const int g = lane >> 2, t = lane & 3;

    // Load combined weights once (tf32-converted, swizzled)
    for (int idx = tid; idx < K * 128; idx += 256) {
        int k = idx >> 7, c = idx & 127;
        float w = (c < 64) ? Wc[k * 64 + c] : Wg[k * 64 + (c - 64)];
        sW[k * 128 + (c ^ ((k & 3) << 3))] = f2tff(w);
    }
    sStat[tid] = 0.f;
    __syncthreads();

    float ssum[8] = {0,0,0,0,0,0,0,0};
    float ssq[8]  = {0,0,0,0,0,0,0,0};

    const int ntiles = (R + 63) >> 6;
    for (int tile = blockIdx.x; tile < ntiles; tile += gridDim.x) {
        const int base = tile << 6;

        // Gather 64-row tile into sA (tf32-converted, swizzled; zero-pad tail)
        for (int idx = tid; idx < 64 * (K / 4); idx += 256) {
            int row = idx & 63;
            int q   = idx >> 6;               // float4 index within row
            int grow = base + row;
            float4 v = make_float4(0.f, 0.f, 0.f, 0.f);
            if (grow < R) {
                int seg = q >> 4;             // 16 float4 per 64-float segment
                int off = q & 15;
                const float* bp; const int* ip;
                if (seg == 0)      { bp = b0; ip = i0; }
                else if (seg == 1) { bp = b1; ip = i1; }
                else if (seg == 2) { bp = b2; ip = i2; }
                else               { bp = b3; ip = i3; }
                int srow = ip ? ip[grow] : grow;
                v = *reinterpret_cast<const float4*>(bp + (size_t)srow * D + off * 4);
            }
            float4 w = make_float4(f2tff(v.x), f2tff(v.y), f2tff(v.z), f2tff(v.w));
            *reinterpret_cast<float4*>(&sA[row * K + ((q * 4) ^ ((row & 7) << 2))]) = w;
        }
        __syncthreads();

        float acc[2][4][4];
        #pragma unroll
        for (int s = 0; s < 2; s++)
            #pragma unroll
            for (int nt = 0; nt < 4; nt++)
                #pragma unroll
                for (int i = 0; i < 4; i++) acc[s][nt][i] = 0.f;

        #pragma unroll 4
        for (int k0 = 0; k0 < K; k0 += 8) {
            uint32_t a[2][4];
            #pragma unroll
            for (int s = 0; s < 2; s++) {
                int r0 = wr * 32 + s * 16 + g;          // (r0+8)&7 == r0&7
                int sw = (r0 & 7) << 2;
                const float* pa = &sA[r0 * K];
                a[s][0] = __float_as_uint(pa[(k0 + t) ^ sw]);
                a[s][1] = __float_as_uint(pa[8 * K + ((k0 + t) ^ sw)]);
                a[s][2] = __float_as_uint(pa[(k0 + t + 4) ^ sw]);
                a[s][3] = __float_as_uint(pa[8 * K + ((k0 + t + 4) ^ sw)]);
            }
            #pragma unroll
            for (int nt = 0; nt < 4; nt++) {
                int c0 = (wc * 32 + nt * 8 + g) ^ (t << 3);
                uint32_t b[2];
                b[0] = __float_as_uint(sW[(k0 + t) * 128 + c0]);
                b[1] = __float_as_uint(sW[(k0 + t + 4) * 128 + c0]);
                mma8(acc[0][nt], a[0], b);
                mma8(acc[1][nt], a[1], b);
            }
        }
        __syncthreads();

        // Store outputs (float2 per row-pair) + accumulate stats
        // (rows >= R produced zero accs -> harmless for sum/sumsq)
        #pragma unroll
        for (int s = 0; s < 2; s++) {
            int row0 = base + wr * 32 + s * 16 + g;
            #pragma unroll
            for (int nt = 0; nt < 4; nt++) {
                int col = wc * 32 + nt * 8 + 2 * t;     // combined col 0..127
                float* outp = (col < 64) ? g_core : g_gate;
                int ocol = col & 63;
                if (row0 < R)
                    *reinterpret_cast<float2*>(&outp[(size_t)row0 * D + ocol]) =
                        make_float2(acc[s][nt][0], acc[s][nt][1]);
                if (row0 + 8 < R)
                    *reinterpret_cast<float2*>(&outp[(size_t)(row0 + 8) * D + ocol]) =
                        make_float2(acc[s][nt][2], acc[s][nt][3]);
                ssum[nt * 2 + 0] += acc[s][nt][0] + acc[s][nt][2];
                ssum[nt * 2 + 1] += acc[s][nt][1] + acc[s][nt][3];
                ssq[nt * 2 + 0]  += acc[s][nt][0] * acc[s][nt][0]
                                  + acc[s][nt][2] * acc[s][nt][2];
                ssq[nt * 2 + 1]  += acc[s][nt][1] * acc[s][nt][1]
                                  + acc[s][nt][3] * acc[s][nt][3];
            }
        }
    }

    // Reduce stats: registers -> shared -> global
    #pragma unroll
    for (int j = 0; j < 8; j++) {
        int col = wc * 32 + (j >> 1) * 8 + 2 * t + (j & 1);
        int sb  = (col < 64) ? 0 : 128;
        int oc  = col & 63;
        atomicAdd(&sStat[sb + oc], ssum[j]);
        atomicAdd(&sStat[sb + 64 + oc], ssq[j]);
    }
    __syncthreads();
    atomicAdd(&g_stats[tid], sStat[tid]);
}

// ---------------------------------------------------------------------------
// Pass 2: finalize BN scale/shift from global stats (1 block, 128 threads)
// ---------------------------------------------------------------------------
__global__ void finalize_kernel(const float* __restrict__ gc, const float* __restrict__ bc,
                                const float* __restrict__ gg, const float* __restrict__ bg,
                                float invR)
{
    int t = threadIdx.x;  // 0..127
    if (t < 64) {
        float mean = g_stats[t] * invR;
        float var  = fmaxf(g_stats[64 + t] * invR - mean * mean, 0.f);
        float sc   = gc[t] * rsqrtf(var + 1e-5f);
        g_norm[t]      = sc;
        g_norm[64 + t] = bc[t] - mean * sc;
    } else {
        int c = t - 64;
        float mean = g_stats[128 + c] * invR;
        float var  = fmaxf(g_stats[192 + c] * invR - mean * mean, 0.f);
        float sc   = gg[c] * rsqrtf(var + 1e-5f);
        g_norm[128 + c] = sc;
        g_norm[192 + c] = bg[c] - mean * sc;
    }
}

__device__ __forceinline__ float sigm(float x) { return 1.f / (1.f + __expf(-x)); }

// ---------------------------------------------------------------------------
// Pass 3a: BN + silu*sigmoid + atomic segment scatter into S
// ---------------------------------------------------------------------------
__global__ void apply_scatter_kernel(const int* __restrict__ seg, float* __restrict__ S, int R)
{
    int idx = blockIdx.x * blockDim.x + threadIdx.x;
    if (idx >= R * 16) return;
    int row = idx >> 4;
    int col = (idx & 15) * 4;
    float4 c4 = *reinterpret_cast<const float4*>(g_core + (size_t)row * D + col);
    float4 g4 = *reinterpret_cast<const float4*>(g_gate + (size_t)row * D + col);
    float cs[4] = {c4.x, c4.y, c4.z, c4.w};
    float gs[4] = {g4.x, g4.y, g4.z, g4.w};
    int s = seg[row];
    float* dst = S + (size_t)s * D + col;
    #pragma unroll
    for (int j = 0; j < 4; j++) {
        float cn = cs[j] * g_norm[col + j] + g_norm[64 + col + j];
        float gn = gs[j] * g_norm[128 + col + j] + g_norm[192 + col + j];
        float m  = cn * sigm(cn) * sigm(gn);
        atomicAdd(dst + j, m);
    }
}

// ---------------------------------------------------------------------------
// Pass 3b: BN + silu*sigmoid + residual write (angle stage, no scatter)
// ---------------------------------------------------------------------------
__global__ void apply_write_kernel(const float* __restrict__ angle, float* __restrict__ dst, int R)
{
    int idx = blockIdx.x * blockDim.x + threadIdx.x;
    if (idx >= R * 16) return;
    int row = idx >> 4;
    int col = (idx & 15) * 4;
    float4 c4 = *reinterpret_cast<const float4*>(g_core + (size_t)row * D + col);
    float4 g4 = *reinterpret_cast<const float4*>(g_gate + (size_t)row * D + col);
    float4 a4 = *reinterpret_cast<const float4*>(angle + (size_t)row * D + col);
    float cs[4] = {c4.x, c4.y, c4.z, c4.w};
    float gs[4] = {g4.x, g4.y, g4.z, g4.w};
    float as[4] = {a4.x, a4.y, a4.z, a4.w};
    float o[4];
    #pragma unroll
    for (int j = 0; j < 4; j++) {
        float cn = cs[j] * g_norm[col + j] + g_norm[64 + col + j];
        float gn = gs[j] * g_norm[128 + col + j] + g_norm[192 + col + j];
        o[j] = cn * sigm(cn) * sigm(gn) + as[j];
    }
    *reinterpret_cast<float4*>(dst + (size_t)row * D + col) =
        make_float4(o[0], o[1], o[2], o[3]);
}

// ---------------------------------------------------------------------------
// Pass 4 (tf32 mma): in-place S[tile,:] = S[tile,:] @ W(64x64) + resid
// Block 256 (8 warps): warp = 16 rows x 32 cols; tile = 64 rows x 64 cols.
// ---------------------------------------------------------------------------
__global__ void __launch_bounds__(256, 1) rowxform_mma(
    float* __restrict__ S, const float* __restrict__ W,
    const float* __restrict__ resid, int R)
{
    __shared__ float sW2[64 * 64];
    __shared__ float sX[64 * 64];
    const int tid  = threadIdx.x;
    const int lane = tid & 31, wid = tid >> 5;
    const int wr = wid >> 1, wc = wid & 1;
    const int g = lane >> 2, t = lane & 3;

    for (int idx = tid; idx < 64 * 64; idx += 256) {
        int k = idx >> 6, c = idx & 63;
        sW2[k * 64 + (c ^ ((k & 3) << 3))] = f2tff(W[idx]);
    }
    __syncthreads();

    const int ntiles = (R + 63) >> 6;
    for (int tile = blockIdx.x; tile < ntiles; tile += gridDim.x) {
        const int base = tile << 6;
        for (int idx = tid; idx < 64 * 16; idx += 256) {
            int row = idx & 63, q = idx >> 6;
            float4 v = make_float4(0.f, 0.f, 0.f, 0.f);
            if (base + row < R)
                v = *reinterpret_cast<const float4*>(&S[(size_t)(base + row) * D + q * 4]);
            float4 w = make_float4(f2tff(v.x), f2tff(v.y), f2tff(v.z), f2tff(v.w));
            *reinterpret_cast<float4*>(&sX[row * 64 + ((q * 4) ^ ((row & 7) << 2))]) = w;
        }
        __syncthreads();

        float acc[4][4];
        #pragma unroll
        for (int nt = 0; nt < 4; nt++)
            #pragma unroll
            for (int i = 0; i < 4; i++) acc[nt][i] = 0.f;

        #pragma unroll
        for (int k0 = 0; k0 < 64; k0 += 8) {
            uint32_t a[4];
            int r0 = wr * 16 + g;
            int sw = (r0 & 7) << 2;
            const float* pa = &sX[r0 * 64];
            a[0] = __float_as_uint(pa[(k0 + t) ^ sw]);
            a[1] = __float_as_uint(pa[8 * 64 + ((k0 + t) ^ sw)]);
            a[2] = __float_as_uint(pa[(k0 + t + 4) ^ sw]);
            a[3] = __float_as_uint(pa[8 * 64 + ((k0 + t + 4) ^ sw)]);
            #pragma unroll
            for (int nt = 0; nt < 4; nt++) {
                int c0 = (wc * 32 + nt * 8 + g) ^ (t << 3);
                uint32_t b[2];
                b[0] = __float_as_uint(sW2[(k0 + t) * 64 + c0]);
                b[1] = __float_as_uint(sW2[(k0 + t + 4) * 64 + c0]);
                mma8(acc[nt], a, b);
            }
        }
        __syncthreads();

        int row0 = base + wr * 16 + g;
        #pragma unroll
        for (int nt = 0; nt < 4; nt++) {
            int col = wc * 32 + nt * 8 + 2 * t;
            if (row0 < R) {
                float2 rr = *reinterpret_cast<const float2*>(&resid[(size_t)row0 * D + col]);
                *reinterpret_cast<float2*>(&S[(size_t)row0 * D + col]) =
                    make_float2(acc[nt][0] + rr.x, acc[nt][1] + rr.y);
            }
            if (row0 + 8 < R) {
                float2 rr = *reinterpret_cast<const float2*>(&resid[(size_t)(row0 + 8) * D + col]);
                *reinterpret_cast<float2*>(&S[(size_t)(row0 + 8) * D + col]) =
                    make_float2(acc[nt][2] + rr.x, acc[nt][3] + rr.y);
            }
        }
    }
}

// ---------------------------------------------------------------------------
// Host orchestration
// ---------------------------------------------------------------------------
extern "C" void kernel_launch(void* const* d_in, const int* in_sizes, int n_in,
                              void* d_out, int out_size)
{
    const bool dictOrder = (n_in >= 4) && (in_sizes[3] > 100000);

    const float *vfeat = (const float*)d_in[0];
    const float *efeat = (const float*)d_in[1];
    const float *afeat = (const float*)d_in[2];
    const float *WcA, *WgA, *WoA, *WcB, *WgB, *WoB, *WcC, *WgC;
    const float *gac, *bac, *gag, *bag, *gbc, *bbc, *gbg, *bbg, *gnc, *bnc, *gng, *bng;
    const int *eidx, *kidx, *iidx, *jidx;

    if (dictOrder) {
        eidx = (const int*)d_in[3];  kidx = (const int*)d_in[4];
        iidx = (const int*)d_in[5];  jidx = (const int*)d_in[6];
        WcA = (const float*)d_in[7];  WgA = (const float*)d_in[8];  WoA = (const float*)d_in[9];
        WcB = (const float*)d_in[10]; WgB = (const float*)d_in[11]; WoB = (const float*)d_in[12];
        WcC = (const float*)d_in[13]; WgC = (const float*)d_in[14];
        gac = (const float*)d_in[15]; gag = (const float*)d_in[16];
        gbc = (const float*)d_in[17]; gbg = (const float*)d_in[18];
        gnc = (const float*)d_in[19]; gng = (const float*)d_in[20];
        bac = (const float*)d_in[21]; bag = (const float*)d_in[22];
        bbc = (const float*)d_in[23]; bbg = (const float*)d_in[24];
        bnc = (const float*)d_in[25]; bng = (const float*)d_in[26];
    } else {
        WcA = (const float*)d_in[3];  WgA = (const float*)d_in[4];  WoA = (const float*)d_in[5];
        WcB = (const float*)d_in[6];  WgB = (const float*)d_in[7];  WoB = (const float*)d_in[8];
        WcC = (const float*)d_in[9];  WgC = (const float*)d_in[10];
        gac = (const float*)d_in[11]; bac = (const float*)d_in[12];
        gag = (const float*)d_in[13]; bag = (const float*)d_in[14];
        gbc = (const float*)d_in[15]; bbc = (const float*)d_in[16];
        gbg = (const float*)d_in[17]; bbg = (const float*)d_in[18];
        gnc = (const float*)d_in[19]; bnc = (const float*)d_in[20];
        gng = (const float*)d_in[21]; bng = (const float*)d_in[22];
        eidx = (const int*)d_in[23]; kidx = (const int*)d_in[24];
        iidx = (const int*)d_in[25]; jidx = (const int*)d_in[26];
    }

    const int N = in_sizes[0] / 64;
    const int E = in_sizes[1] / 64;
    const int T = in_sizes[2] / 64;
    const int* src = eidx;
    const int* dst = eidx + E;

    float* out  = (float*)d_out;
    float* vnew = out;                          // [N,64]
    float* enew = out + (size_t)N * 64;         // [E,64]
    float* anew = out + (size_t)(N + E) * 64;   // [T,64]

    float* stats_ptr = nullptr;
    cudaGetSymbolAddress((void**)&stats_ptr, g_stats);

    int dev = 0;  cudaGetDevice(&dev);
    int sm = 148; cudaDeviceGetAttribute(&sm, cudaDevAttrMultiProcessorCount, dev);

    const size_t smemA = (size_t)(192 * 128 + 64 * 192 + 256) * 4;  // ~145 KB
    const size_t smemB = (size_t)(256 * 128 + 64 * 256 + 256) * 4;  // ~193 KB
    cudaFuncSetAttribute(pass1_mma<192>, cudaFuncAttributeMaxDynamicSharedMemorySize, (int)smemA);
    cudaFuncSetAttribute(pass1_mma<256>, cudaFuncAttributeMaxDynamicSharedMemorySize, (int)smemB);

    // Zero segment-sum accumulators (d_out is poisoned by the harness)
    cudaMemsetAsync(vnew, 0, (size_t)N * 64 * sizeof(float));
    cudaMemsetAsync(enew, 0, (size_t)E * 64 * sizeof(float));

    // ---------------- Stage A: AtomConvCat ----------------
    cudaMemsetAsync(stats_ptr, 0, 256 * sizeof(float));
    pass1_mma<192><<<sm, 256, smemA>>>(
        vfeat, src, efeat, nullptr, vfeat, dst, nullptr, nullptr, WcA, WgA, E);
    finalize_kernel<<<1, 128>>>(gac, bac, gag, bag, 1.f / (float)E);
    apply_scatter_kernel<<<(E * 16 + 255) / 256, 256>>>(src, vnew, E);
    rowxform_mma<<<sm * 4, 256>>>(vnew, WoA, vfeat, N);

    // ---------------- Stage B: BondConvCat ----------------
    cudaMemsetAsync(stats_ptr, 0, 256 * sizeof(float));
    pass1_mma<256><<<sm, 256, smemB>>>(
        vnew, jidx, efeat, kidx, efeat, iidx, afeat, nullptr, WcB, WgB, T);
    finalize_kernel<<<1, 128>>>(gbc, bbc, gbg, bbg, 1.f / (float)T);
    apply_scatter_kernel<<<(T * 16 + 255) / 256, 256>>>(kidx, enew, T);
    rowxform_mma<<<sm * 4, 256>>>(enew, WoB, efeat, E);

    // ---------------- Stage C: AngleConvCat ----------------
    cudaMemsetAsync(stats_ptr, 0, 256 * sizeof(float));
    pass1_mma<256><<<sm, 256, smemB>>>(
        vnew, jidx, enew, kidx, enew, iidx, afeat, nullptr, WcC, WgC, T);
    finalize_kernel<<<1, 128>>>(gnc, bnc, gng, bng, 1.f / (float)T);
    apply_write_kernel<<<(T * 16 + 255) / 256, 256>>>(afeat, anew, T);
}

// round 3
// speedup vs baseline: 3.4824x; 2.2320x over previous
#include <cuda_runtime.h>
#include <cuda_fp16.h>
#include <cstdint>

#define D 64
#define MAXROWS 616000

// Scratch (device globals: allocation-free rule) — fp16 pre-activations
__device__ __half g_coreh[(size_t)MAXROWS * D];
__device__ __half g_gateh[(size_t)MAXROWS * D];
__device__ float g_stats[4 * D];   // sum_c | sumsq_c | sum_g | sumsq_g
__device__ float g_norm[4 * D];    // scale_c | shift_c | scale_g | shift_g

__device__ __forceinline__ uint32_t f2tf(float f) {
    uint32_t r; asm("cvt.rna.tf32.f32 %0, %1;" : "=r"(r) : "f"(f)); return r;
}
__device__ __forceinline__ float f2tff(float f) { return __uint_as_float(f2tf(f)); }

__device__ __forceinline__ void mma8(float c[4], const uint32_t a[4], const uint32_t b[2]) {
    asm volatile("mma.sync.aligned.m16n8k8.row.col.f32.tf32.tf32.f32 "
        "{%0,%1,%2,%3}, {%4,%5,%6,%7}, {%8,%9}, {%0,%1,%2,%3};\n"
        : "+f"(c[0]), "+f"(c[1]), "+f"(c[2]), "+f"(c[3])
        : "r"(a[0]), "r"(a[1]), "r"(a[2]), "r"(a[3]), "r"(b[0]), "r"(b[1]));
}

__device__ __forceinline__ void cpasync16(void* smem_dst, const void* gmem_src, int sz) {
    uint32_t d = (uint32_t)__cvta_generic_to_shared(smem_dst);
    asm volatile("cp.async.ca.shared.global [%0], [%1], 16, %2;"
                 :: "r"(d), "l"(gmem_src), "r"(sz));
}

// ---------------------------------------------------------------------------
// Pass 1: pipelined gather (cp.async double-buffer, 64-col chunks == segments)
// + dual tf32 GEMM (core|gate, 128 cols) + per-feature stats.
// Block = 512 threads (16 warps), tile = 128 rows x 128 cols, warp = 32x32.
// sW[K][128] swizzled (c ^ ((k&3)<<3)); sA[128][64] swizzled ((f) ^ ((row&7)<<2)).
// ---------------------------------------------------------------------------
template<int K, int NSEG>
__global__ void __launch_bounds__(512, 1) pass1_mma(
    const float* __restrict__ b0, const int* __restrict__ i0,
    const float* __restrict__ b1, const int* __restrict__ i1,
    const float* __restrict__ b2, const int* __restrict__ i2,
    const float* __restrict__ b3, const int* __restrict__ i3,
    const float* __restrict__ Wc, const float* __restrict__ Wg,
    int R)
{
    extern __shared__ float smem[];
    float* sW   = smem;                   // K*128
    float* sA0  = smem + K * 128;         // 128*64
    float* sA1  = sA0 + 128 * 64;         // 128*64
    int*   sIdx = (int*)(sA1 + 128 * 64); // NSEG*128 (padded to 512)
    float* sStat = (float*)(sIdx + 512);  // 256

    const int tid  = threadIdx.x;
    const int lane = tid & 31, wid = tid >> 5;
    const int wr = wid >> 2, wc = wid & 3;
    const int g = lane >> 2, t = lane & 3;

    for (int idx = tid; idx < K * 128; idx += 512) {
        int k = idx >> 7, c = idx & 127;
        float w = (c < 64) ? Wc[k * 64 + c] : Wg[k * 64 + (c - 64)];
        sW[k * 128 + (c ^ ((k & 3) << 3))] = f2tff(w);
    }
    if (tid < 256) sStat[tid] = 0.f;
    __syncthreads();

    float ssum[8] = {0,0,0,0,0,0,0,0};
    float ssq[8]  = {0,0,0,0,0,0,0,0};

    const float* bps[4] = {b0, b1, b2, b3};

    const int ntiles = (R + 127) >> 7;
    for (int tile = blockIdx.x; tile < ntiles; tile += gridDim.x) {
        const int base = tile << 7;

        // Resolve indices for this tile (NSEG*128 entries)
        if (tid < NSEG * 128) {
            int s = tid >> 7, r = tid & 127;
            int grow = base + r;
            const int* ip = (s == 0) ? i0 : (s == 1) ? i1 : (s == 2) ? i2 : i3;
            int srow = 0;
            if (grow < R) srow = ip ? ip[grow] : grow;
            sIdx[tid] = srow;
        }
        __syncthreads();

        // Issue chunk q into buffer sB
        auto issue = [&](int q, float* sB) {
            const float* bp = bps[q];
            #pragma unroll
            for (int i = 0; i < 4; i++) {
                int idx = tid + i * 512;      // 0..2047
                int row = idx >> 4;           // 0..127
                int f4  = idx & 15;
                int srow = sIdx[q * 128 + row];
                int sz = (base + row < R) ? 16 : 0;
                cpasync16(&sA0[(sB - sA0) + row * 64 + ((f4 * 4) ^ ((row & 7) << 2))],
                          bp + (size_t)srow * D + f4 * 4, sz);
            }
            asm volatile("cp.async.commit_group;");
        };

        float acc[2][4][4];
        #pragma unroll
        for (int s = 0; s < 2; s++)
            #pragma unroll
            for (int nt = 0; nt < 4; nt++)
                #pragma unroll
                for (int i = 0; i < 4; i++) acc[s][nt][i] = 0.f;

        issue(0, sA0);
        #pragma unroll
        for (int q = 0; q < NSEG; q++) {
            if (q + 1 < NSEG) {
                issue(q + 1, ((q + 1) & 1) ? sA1 : sA0);
                asm volatile("cp.async.wait_group 1;");
            } else {
                asm volatile("cp.async.wait_group 0;");
            }
            __syncthreads();
            float* sB = (q & 1) ? sA1 : sA0;

            #pragma unroll
            for (int kk = 0; kk < 64; kk += 8) {
                uint32_t a[2][4];
                #pragma unroll
                for (int s = 0; s < 2; s++) {
                    int r0 = wr * 32 + s * 16 + g;
                    int sw = (r0 & 7) << 2;
                    const float* pa = &sB[r0 * 64];
                    a[s][0] = __float_as_uint(pa[(kk + t) ^ sw]);
                    a[s][1] = __float_as_uint(pa[8 * 64 + ((kk + t) ^ sw)]);
                    a[s][2] = __float_as_uint(pa[(kk + t + 4) ^ sw]);
                    a[s][3] = __float_as_uint(pa[8 * 64 + ((kk + t + 4) ^ sw)]);
                }
                int kg = q * 64 + kk;
                #pragma unroll
                for (int nt = 0; nt < 4; nt++) {
                    int c0 = (wc * 32 + nt * 8 + g) ^ (t << 3);
                    uint32_t b[2];
                    b[0] = __float_as_uint(sW[(kg + t) * 128 + c0]);
                    b[1] = __float_as_uint(sW[(kg + t + 4) * 128 + c0]);
                    mma8(acc[0][nt], a[0], b);
                    mma8(acc[1][nt], a[1], b);
                }
            }
            __syncthreads();
        }

        // Store fp16 outputs + accumulate stats (tail rows have zero accs)
        #pragma unroll
        for (int s = 0; s < 2; s++) {
            int row0 = base + wr * 32 + s * 16 + g;
            #pragma unroll
            for (int nt = 0; nt < 4; nt++) {
                int col = wc * 32 + nt * 8 + 2 * t;
                __half* outp = (col < 64) ? g_coreh : g_gateh;
                int ocol = col & 63;
                if (row0 < R)
                    *reinterpret_cast<__half2*>(&outp[(size_t)row0 * D + ocol]) =
                        __floats2half2_rn(acc[s][nt][0], acc[s][nt][1]);
                if (row0 + 8 < R)
                    *reinterpret_cast<__half2*>(&outp[(size_t)(row0 + 8) * D + ocol]) =
                        __floats2half2_rn(acc[s][nt][2], acc[s][nt][3]);
                ssum[nt * 2 + 0] += acc[s][nt][0] + acc[s][nt][2];
                ssum[nt * 2 + 1] += acc[s][nt][1] + acc[s][nt][3];
                ssq[nt * 2 + 0]  += acc[s][nt][0] * acc[s][nt][0]
                                  + acc[s][nt][2] * acc[s][nt][2];
                ssq[nt * 2 + 1]  += acc[s][nt][1] * acc[s][nt][1]
                                  + acc[s][nt][3] * acc[s][nt][3];
            }
        }
    }

    #pragma unroll
    for (int j = 0; j < 8; j++) {
        int col = wc * 32 + (j >> 1) * 8 + 2 * t + (j & 1);
        int sb  = (col < 64) ? 0 : 128;
        int oc  = col & 63;
        atomicAdd(&sStat[sb + oc], ssum[j]);
        atomicAdd(&sStat[sb + 64 + oc], ssq[j]);
    }
    __syncthreads();
    if (tid < 256) atomicAdd(&g_stats[tid], sStat[tid]);
}

// ---------------------------------------------------------------------------
// Finalize BN scale/shift (1 block, 128 threads)
// ---------------------------------------------------------------------------
__global__ void finalize_kernel(const float* __restrict__ gc, const float* __restrict__ bc,
                                const float* __restrict__ gg, const float* __restrict__ bg,
                                float invR)
{
    int t = threadIdx.x;
    if (t < 64) {
        float mean = g_stats[t] * invR;
        float var  = fmaxf(g_stats[64 + t] * invR - mean * mean, 0.f);
        float sc   = gc[t] * rsqrtf(var + 1e-5f);
        g_norm[t]      = sc;
        g_norm[64 + t] = bc[t] - mean * sc;
    } else {
        int c = t - 64;
        float mean = g_stats[128 + c] * invR;
        float var  = fmaxf(g_stats[192 + c] * invR - mean * mean, 0.f);
        float sc   = gg[c] * rsqrtf(var + 1e-5f);
        g_norm[128 + c] = sc;
        g_norm[192 + c] = bg[c] - mean * sc;
    }
}

__device__ __forceinline__ float sigm(float x) { return 1.f / (1.f + __expf(-x)); }

// ---------------------------------------------------------------------------
// BN + silu*sigmoid + vectorized atomic segment scatter (v4 red)
// Thread handles 8 columns of one row.
// ---------------------------------------------------------------------------
__global__ void apply_scatter_kernel(const int* __restrict__ seg, float* __restrict__ S, int R)
{
    int idx = blockIdx.x * blockDim.x + threadIdx.x;
    if (idx >= R * 8) return;
    int row = idx >> 3;
    int col = (idx & 7) * 8;
    const __half2* cp = reinterpret_cast<const __half2*>(g_coreh + (size_t)row * D + col);
    const __half2* gp = reinterpret_cast<const __half2*>(g_gateh + (size_t)row * D + col);
    float m[8];
    #pragma unroll
    for (int j = 0; j < 4; j++) {
        float2 c2 = __half22float2(cp[j]);
        float2 g2 = __half22float2(gp[j]);
        int cc = col + 2 * j;
        float cn0 = c2.x * g_norm[cc]     + g_norm[64 + cc];
        float cn1 = c2.y * g_norm[cc + 1] + g_norm[64 + cc + 1];
        float gn0 = g2.x * g_norm[128 + cc]     + g_norm[192 + cc];
        float gn1 = g2.y * g_norm[128 + cc + 1] + g_norm[192 + cc + 1];
        m[2 * j]     = cn0 * sigm(cn0) * sigm(gn0);
        m[2 * j + 1] = cn1 * sigm(cn1) * sigm(gn1);
    }
    int s = seg[row];
    float* dst = S + (size_t)s * D + col;
    asm volatile("red.global.add.v4.f32 [%0], {%1,%2,%3,%4};"
                 :: "l"(dst), "f"(m[0]), "f"(m[1]), "f"(m[2]), "f"(m[3]) : "memory");
    asm volatile("red.global.add.v4.f32 [%0], {%1,%2,%3,%4};"
                 :: "l"(dst + 4), "f"(m[4]), "f"(m[5]), "f"(m[6]), "f"(m[7]) : "memory");
}

// ---------------------------------------------------------------------------
// BN + silu*sigmoid + residual write (angle stage)
// ---------------------------------------------------------------------------
__global__ void apply_write_kernel(const float* __restrict__ angle, float* __restrict__ dst, int R)
{
    int idx = blockIdx.x * blockDim.x + threadIdx.x;
    if (idx >= R * 8) return;
    int row = idx >> 3;
    int col = (idx & 7) * 8;
    const __half2* cp = reinterpret_cast<const __half2*>(g_coreh + (size_t)row * D + col);
    const __half2* gp = reinterpret_cast<const __half2*>(g_gateh + (size_t)row * D + col);
    float4 a0 = *reinterpret_cast<const float4*>(angle + (size_t)row * D + col);
    float4 a1 = *reinterpret_cast<const float4*>(angle + (size_t)row * D + col + 4);
    float av[8] = {a0.x, a0.y, a0.z, a0.w, a1.x, a1.y, a1.z, a1.w};
    float o[8];
    #pragma unroll
    for (int j = 0; j < 4; j++) {
        float2 c2 = __half22float2(cp[j]);
        float2 g2 = __half22float2(gp[j]);
        int cc = col + 2 * j;
        float cn0 = c2.x * g_norm[cc]     + g_norm[64 + cc];
        float cn1 = c2.y * g_norm[cc + 1] + g_norm[64 + cc + 1];
        float gn0 = g2.x * g_norm[128 + cc]     + g_norm[192 + cc];
        float gn1 = g2.y * g_norm[128 + cc + 1] + g_norm[192 + cc + 1];
        o[2 * j]     = cn0 * sigm(cn0) * sigm(gn0) + av[2 * j];
        o[2 * j + 1] = cn1 * sigm(cn1) * sigm(gn1) + av[2 * j + 1];
    }
    *reinterpret_cast<float4*>(dst + (size_t)row * D + col) =
        make_float4(o[0], o[1], o[2], o[3]);
    *reinterpret_cast<float4*>(dst + (size_t)row * D + col + 4) =
        make_float4(o[4], o[5], o[6], o[7]);
}

// ---------------------------------------------------------------------------
// Row transform (tf32 mma): S[tile,:] = S[tile,:] @ W(64x64) + resid
// Non-persistent: one 64-row tile per block (256 threads, 8 warps).
// ---------------------------------------------------------------------------
__global__ void __launch_bounds__(256) rowxform_mma(
    float* __restrict__ S, const float* __restrict__ W,
    const float* __restrict__ resid, int R)
{
    __shared__ float sW2[64 * 64];
    __shared__ float sX[64 * 64];
    const int tid  = threadIdx.x;
    const int lane = tid & 31, wid = tid >> 5;
    const int wr = wid >> 1, wc = wid & 1;
    const int g = lane >> 2, t = lane & 3;

    for (int idx = tid; idx < 64 * 64; idx += 256) {
        int k = idx >> 6, c = idx & 63;
        sW2[k * 64 + (c ^ ((k & 3) << 3))] = f2tff(W[idx]);
    }

    const int base = blockIdx.x << 6;
    for (int idx = tid; idx < 64 * 16; idx += 256) {
        int row = idx & 63, q = idx >> 6;
        float4 v = make_float4(0.f, 0.f, 0.f, 0.f);
        if (base + row < R)
            v = *reinterpret_cast<const float4*>(&S[(size_t)(base + row) * D + q * 4]);
        *reinterpret_cast<float4*>(&sX[row * 64 + ((q * 4) ^ ((row & 7) << 2))]) = v;
    }
    __syncthreads();

    float acc[4][4];
    #pragma unroll
    for (int nt = 0; nt < 4; nt++)
        #pragma unroll
        for (int i = 0; i < 4; i++) acc[nt][i] = 0.f;

    #pragma unroll
    for (int k0 = 0; k0 < 64; k0 += 8) {
        uint32_t a[4];
        int r0 = wr * 16 + g;
        int sw = (r0 & 7) << 2;
        const float* pa = &sX[r0 * 64];
        a[0] = __float_as_uint(pa[(k0 + t) ^ sw]);
        a[1] = __float_as_uint(pa[8 * 64 + ((k0 + t) ^ sw)]);
        a[2] = __float_as_uint(pa[(k0 + t + 4) ^ sw]);
        a[3] = __float_as_uint(pa[8 * 64 + ((k0 + t + 4) ^ sw)]);
        #pragma unroll
        for (int nt = 0; nt < 4; nt++) {
            int c0 = (wc * 32 + nt * 8 + g) ^ (t << 3);
            uint32_t b[2];
            b[0] = __float_as_uint(sW2[(k0 + t) * 64 + c0]);
            b[1] = __float_as_uint(sW2[(k0 + t + 4) * 64 + c0]);
            mma8(acc[nt], a, b);
        }
    }

    int row0 = base + wr * 16 + g;
    #pragma unroll
    for (int nt = 0; nt < 4; nt++) {
        int col = wc * 32 + nt * 8 + 2 * t;
        if (row0 < R) {
            float2 rr = *reinterpret_cast<const float2*>(&resid[(size_t)row0 * D + col]);
            *reinterpret_cast<float2*>(&S[(size_t)row0 * D + col]) =
                make_float2(acc[nt][0] + rr.x, acc[nt][1] + rr.y);
        }
        if (row0 + 8 < R) {
            float2 rr = *reinterpret_cast<const float2*>(&resid[(size_t)(row0 + 8) * D + col]);
            *reinterpret_cast<float2*>(&S[(size_t)(row0 + 8) * D + col]) =
                make_float2(acc[nt][2] + rr.x, acc[nt][3] + rr.y);
        }
    }
}

// ---------------------------------------------------------------------------
// Host orchestration
// ---------------------------------------------------------------------------
extern "C" void kernel_launch(void* const* d_in, const int* in_sizes, int n_in,
                              void* d_out, int out_size)
{
    const bool dictOrder = (n_in >= 4) && (in_sizes[3] > 100000);

    const float *vfeat = (const float*)d_in[0];
    const float *efeat = (const float*)d_in[1];
    const float *afeat = (const float*)d_in[2];
    const float *WcA, *WgA, *WoA, *WcB, *WgB, *WoB, *WcC, *WgC;
    const float *gac, *bac, *gag, *bag, *gbc, *bbc, *gbg, *bbg, *gnc, *bnc, *gng, *bng;
    const int *eidx, *kidx, *iidx, *jidx;

    if (dictOrder) {
        eidx = (const int*)d_in[3];  kidx = (const int*)d_in[4];
        iidx = (const int*)d_in[5];  jidx = (const int*)d_in[6];
        WcA = (const float*)d_in[7];  WgA = (const float*)d_in[8];  WoA = (const float*)d_in[9];
        WcB = (const float*)d_in[10]; WgB = (const float*)d_in[11]; WoB = (const float*)d_in[12];
        WcC = (const float*)d_in[13]; WgC = (const float*)d_in[14];
        gac = (const float*)d_in[15]; gag = (const float*)d_in[16];
        gbc = (const float*)d_in[17]; gbg = (const float*)d_in[18];
        gnc = (const float*)d_in[19]; gng = (const float*)d_in[20];
        bac = (const float*)d_in[21]; bag = (const float*)d_in[22];
        bbc = (const float*)d_in[23]; bbg = (const float*)d_in[24];
        bnc = (const float*)d_in[25]; bng = (const float*)d_in[26];
    } else {
        WcA = (const float*)d_in[3];  WgA = (const float*)d_in[4];  WoA = (const float*)d_in[5];
        WcB = (const float*)d_in[6];  WgB = (const float*)d_in[7];  WoB = (const float*)d_in[8];
        WcC = (const float*)d_in[9];  WgC = (const float*)d_in[10];
        gac = (const float*)d_in[11]; bac = (const float*)d_in[12];
        gag = (const float*)d_in[13]; bag = (const float*)d_in[14];
        gbc = (const float*)d_in[15]; bbc = (const float*)d_in[16];
        gbg = (const float*)d_in[17]; bbg = (const float*)d_in[18];
        gnc = (const float*)d_in[19]; bnc = (const float*)d_in[20];
        gng = (const float*)d_in[21]; bng = (const float*)d_in[22];
        eidx = (const int*)d_in[23]; kidx = (const int*)d_in[24];
        iidx = (const int*)d_in[25]; jidx = (const int*)d_in[26];
    }

    const int N = in_sizes[0] / 64;
    const int E = in_sizes[1] / 64;
    const int T = in_sizes[2] / 64;
    const int* src = eidx;
    const int* dst = eidx + E;

    float* out  = (float*)d_out;
    float* vnew = out;                          // [N,64]
    float* enew = out + (size_t)N * 64;         // [E,64]
    float* anew = out + (size_t)(N + E) * 64;   // [T,64]

    float* stats_ptr = nullptr;
    cudaGetSymbolAddress((void**)&stats_ptr, g_stats);

    int dev = 0;  cudaGetDevice(&dev);
    int sm = 148; cudaDeviceGetAttribute(&sm, cudaDevAttrMultiProcessorCount, dev);

    const size_t smemA = (size_t)(192 * 128 + 2 * 128 * 64 + 512 + 256) * 4;  // ~166 KB
    const size_t smemB = (size_t)(256 * 128 + 2 * 128 * 64 + 512 + 256) * 4;  // ~198 KB
    cudaFuncSetAttribute(pass1_mma<192, 3>, cudaFuncAttributeMaxDynamicSharedMemorySize, (int)smemA);
    cudaFuncSetAttribute(pass1_mma<256, 4>, cudaFuncAttributeMaxDynamicSharedMemorySize, (int)smemB);

    cudaMemsetAsync(vnew, 0, (size_t)N * 64 * sizeof(float));
    cudaMemsetAsync(enew, 0, (size_t)E * 64 * sizeof(float));

    // ---------------- Stage A: AtomConvCat ----------------
    cudaMemsetAsync(stats_ptr, 0, 256 * sizeof(float));
    pass1_mma<192, 3><<<sm, 512, smemA>>>(
        vfeat, src, efeat, nullptr, vfeat, dst, nullptr, nullptr, WcA, WgA, E);
    finalize_kernel<<<1, 128>>>(gac, bac, gag, bag, 1.f / (float)E);
    apply_scatter_kernel<<<(E * 8 + 255) / 256, 256>>>(src, vnew, E);
    rowxform_mma<<<(N + 63) / 64, 256>>>(vnew, WoA, vfeat, N);

    // ---------------- Stage B: BondConvCat ----------------
    cudaMemsetAsync(stats_ptr, 0, 256 * sizeof(float));
    pass1_mma<256, 4><<<sm, 512, smemB>>>(
        vnew, jidx, efeat, kidx, efeat, iidx, afeat, nullptr, WcB, WgB, T);
    finalize_kernel<<<1, 128>>>(gbc, bbc, gbg, bbg, 1.f / (float)T);
    apply_scatter_kernel<<<(T * 8 + 255) / 256, 256>>>(kidx, enew, T);
    rowxform_mma<<<(E + 63) / 64, 256>>>(enew, WoB, efeat, E);

    // ---------------- Stage C: AngleConvCat ----------------
    cudaMemsetAsync(stats_ptr, 0, 256 * sizeof(float));
    pass1_mma<256, 4><<<sm, 512, smemB>>>(
        vnew, jidx, enew, kidx, enew, iidx, afeat, nullptr, WcC, WgC, T);
    finalize_kernel<<<1, 128>>>(gnc, bnc, gng, bng, 1.f / (float)T);
    apply_write_kernel<<<(T * 8 + 255) / 256, 256>>>(afeat, anew, T);
}